// round 2
// baseline (speedup 1.0000x reference)
#include <cuda_runtime.h>
#include <cstdint>

typedef unsigned long long ull;

#define NSEQ 480
#define TLEN 200
#define CH   64
#define HID  128
#define G4   512
#define NROW (NSEQ * TLEN)   // 96000

// ---------------- device scratch (no allocs allowed) ----------------
__device__ float g_xf[NROW * CH];      // [t][seq][c]            24.6 MB
__device__ float g_xg[NROW * G4];      // [t][seq][g]           196.6 MB
__device__ float g_Wp[HID * HID * 4];  // [k][r][{i,f,g,o}]      256 KB
__device__ float g_Wiht[CH * G4];      // [c][g]
__device__ float g_bias[G4];           // b_ih + b_hh

// ---------------- f32x2 helpers ----------------
__device__ __forceinline__ ull pk2(float lo, float hi) {
    ull r; asm("mov.b64 %0, {%1, %2};" : "=l"(r) : "f"(lo), "f"(hi)); return r;
}
__device__ __forceinline__ void upk2(ull v, float& lo, float& hi) {
    asm("mov.b64 {%0, %1}, %2;" : "=f"(lo), "=f"(hi) : "l"(v));
}
__device__ __forceinline__ void fma2(ull& a, ull b, ull c) {
    asm("fma.rn.f32x2 %0, %1, %2, %0;" : "+l"(a) : "l"(b), "l"(c));
}
__device__ __forceinline__ void add2(ull& a, ull b) {
    asm("add.rn.f32x2 %0, %0, %1;" : "+l"(a) : "l"(b));
}

// ---------------- prep: transpose/pack weights, fold bias ----------------
__global__ void __launch_bounds__(256) prep_kernel(
    const float* __restrict__ Wih, const float* __restrict__ Whh,
    const float* __restrict__ bih, const float* __restrict__ bhh)
{
    int idx = blockIdx.x * 256 + threadIdx.x;
    if (idx < HID * HID * 4) {
        int qg = idx & 3, r = (idx >> 2) & 127, k = idx >> 9;
        g_Wp[idx] = Whh[(qg * 128 + r) * 128 + k];   // W_hh[(gate*128+r)][k]
    }
    if (idx < CH * G4) {
        int c = idx >> 9, g = idx & 511;
        g_Wiht[idx] = Wih[g * 64 + c];               // W_ih[g][c]
    }
    if (idx < G4) g_bias[idx] = bih[idx] + bhh[idx];
}

// ---------------- transpose x: (B,C,T,P) -> xf[t][seq=b*30+p][c] ----------------
__global__ void __launch_bounds__(256) transp_kernel(const float* __restrict__ x)
{
    __shared__ float tile[64 * 30];
    int t = blockIdx.x, b = blockIdx.y;
    for (int idx = threadIdx.x; idx < 64 * 30; idx += 256) {
        int c = idx / 30, p = idx - c * 30;
        tile[idx] = x[(b * 64 + c) * 6000 + t * 30 + p];
    }
    __syncthreads();
    for (int idx = threadIdx.x; idx < 64 * 30; idx += 256) {
        int p = idx >> 6, c = idx & 63;
        g_xf[(t * NSEQ + b * 30 + p) * 64 + c] = tile[c * 30 + p];
    }
}

// ---------------- xg GEMM: xg = xf @ Wiht + bias  (M=96000, N=512, K=64) ----------------
__global__ void __launch_bounds__(256) gemm_kernel()
{
    __shared__ float As[64 * 68];   // [k][m], pad 68 for alignment
    __shared__ float Bs[64 * 64];   // [k][n]
    int tid = threadIdx.x;
    int row0 = blockIdx.x * 64, col0 = blockIdx.y * 64;

    for (int idx = tid; idx < 4096; idx += 256) {
        int m = idx >> 6, k = idx & 63;
        As[k * 68 + m] = g_xf[(row0 + m) * 64 + k];
    }
    for (int idx = tid; idx < 4096; idx += 256) {
        int k = idx >> 6, n = idx & 63;
        Bs[idx] = g_Wiht[k * 512 + col0 + n];
    }
    __syncthreads();

    int tm = tid & 15, tn = tid >> 4;
    int m0 = tm * 4, n0 = tn * 4;
    ull c01[4] = {0, 0, 0, 0}, c23[4] = {0, 0, 0, 0};

#pragma unroll 16
    for (int k = 0; k < 64; k++) {
        float4 av = *(const float4*)&As[k * 68 + m0];
        longlong2 bv = *(const longlong2*)&Bs[k * 64 + n0];
        ull b01 = (ull)bv.x, b23 = (ull)bv.y;
        ull a0 = pk2(av.x, av.x), a1 = pk2(av.y, av.y);
        ull a2 = pk2(av.z, av.z), a3 = pk2(av.w, av.w);
        fma2(c01[0], b01, a0); fma2(c23[0], b23, a0);
        fma2(c01[1], b01, a1); fma2(c23[1], b23, a1);
        fma2(c01[2], b01, a2); fma2(c23[2], b23, a2);
        fma2(c01[3], b01, a3); fma2(c23[3], b23, a3);
    }

    float4 bi = *(const float4*)&g_bias[col0 + n0];
#pragma unroll
    for (int i = 0; i < 4; i++) {
        float r0, r1, r2, r3;
        upk2(c01[i], r0, r1); upk2(c23[i], r2, r3);
        float4 res = make_float4(r0 + bi.x, r1 + bi.y, r2 + bi.z, r3 + bi.w);
        *(float4*)&g_xg[(row0 + m0 + i) * 512 + col0 + n0] = res;
    }
}

// ---------------- persistent LSTM + FC ----------------
// smem layout (dynamic):
#define LS_WS   0                        // 64*128 longlong2 (128 KB): W_hh k in [32q+16,32q+32)
#define LS_XB   (128 * 1024)             // 2 * 512 float4 (16 KB): xg double buffer
#define LS_PIF  (LS_XB + 16384)          // 16*128 ull (16 KB): partials {i,f}
#define LS_PGO  (LS_PIF + 16384)         // 16*128 ull (16 KB): partials {g,o}
#define LS_H    (LS_PGO + 16384)         // 512 float (2 KB): h[k][s]
#define LS_TOTAL (LS_H + 2048)           // 182272 B

__global__ void __launch_bounds__(512, 1) lstm_kernel(
    const float* __restrict__ Wfc, const float* __restrict__ bfc,
    float* __restrict__ out)
{
    extern __shared__ char smem[];
    longlong2* Ws2 = (longlong2*)(smem + LS_WS);
    float4*    xb4 = (float4*)(smem + LS_XB);
    ull*       pIF = (ull*)(smem + LS_PIF);
    ull*       pGO = (ull*)(smem + LS_PGO);
    float*     hsm = (float*)(smem + LS_H);
    const float4* hs4 = (const float4*)hsm;

    int tid = threadIdx.x;
    int r = tid & 127, q = tid >> 7;
    int s0 = blockIdx.x * 4;

    // register-resident half of W_hh: k in [32q, 32q+16)
    ull WIF[16], WGO[16];
    const longlong2* Wp2 = (const longlong2*)g_Wp;
#pragma unroll
    for (int kk = 0; kk < 16; kk++) {
        longlong2 v = Wp2[(32 * q + kk) * 128 + r];
        WIF[kk] = (ull)v.x; WGO[kk] = (ull)v.y;
    }
    // smem-resident half: k in [32q+16, 32q+32)
    for (int idx = tid; idx < 64 * 128; idx += 512) {
        int kidx = idx >> 7, rr = idx & 127;
        int qq = kidx >> 4, kk = (kidx & 15) + 16;
        Ws2[idx] = Wp2[(32 * qq + kk) * 128 + rr];
    }

    hsm[tid < 512 ? tid : 0] = 0.f;
    const float4* xg4 = (const float4*)g_xg;
    xb4[tid] = xg4[(0 * NSEQ + s0) * 128 + tid];   // preload t=0 into buffer 0

    float cst = 0.f;                // c-state for (r2, s2)
    int r2 = tid & 127, s2 = tid >> 7;
    __syncthreads();

#pragma unroll 1
    for (int t = 0; t < TLEN; t++) {
        // prefetch next step's xg
        float4 nx = make_float4(0.f, 0.f, 0.f, 0.f);
        if (t + 1 < TLEN) nx = xg4[((t + 1) * NSEQ + s0) * 128 + tid];

        ull aIF0 = 0, aIF1 = 0, aIF2 = 0, aIF3 = 0;
        ull aGO0 = 0, aGO1 = 0, aGO2 = 0, aGO3 = 0;

#pragma unroll
        for (int kk = 0; kk < 16; kk++) {            // register-W half
            float4 hv = hs4[32 * q + kk];
            ull h0 = pk2(hv.x, hv.x), h1 = pk2(hv.y, hv.y);
            ull h2 = pk2(hv.z, hv.z), h3 = pk2(hv.w, hv.w);
            fma2(aIF0, WIF[kk], h0); fma2(aGO0, WGO[kk], h0);
            fma2(aIF1, WIF[kk], h1); fma2(aGO1, WGO[kk], h1);
            fma2(aIF2, WIF[kk], h2); fma2(aGO2, WGO[kk], h2);
            fma2(aIF3, WIF[kk], h3); fma2(aGO3, WGO[kk], h3);
        }
#pragma unroll
        for (int kk = 0; kk < 16; kk++) {            // smem-W half
            longlong2 wv = Ws2[(q * 16 + kk) * 128 + r];
            ull wIF = (ull)wv.x, wGO = (ull)wv.y;
            float4 hv = hs4[32 * q + 16 + kk];
            ull h0 = pk2(hv.x, hv.x), h1 = pk2(hv.y, hv.y);
            ull h2 = pk2(hv.z, hv.z), h3 = pk2(hv.w, hv.w);
            fma2(aIF0, wIF, h0); fma2(aGO0, wGO, h0);
            fma2(aIF1, wIF, h1); fma2(aGO1, wGO, h1);
            fma2(aIF2, wIF, h2); fma2(aGO2, wGO, h2);
            fma2(aIF3, wIF, h3); fma2(aGO3, wGO, h3);
        }

        pIF[(q * 4 + 0) * 128 + r] = aIF0;  pGO[(q * 4 + 0) * 128 + r] = aGO0;
        pIF[(q * 4 + 1) * 128 + r] = aIF1;  pGO[(q * 4 + 1) * 128 + r] = aGO1;
        pIF[(q * 4 + 2) * 128 + r] = aIF2;  pGO[(q * 4 + 2) * 128 + r] = aGO2;
        pIF[(q * 4 + 3) * 128 + r] = aIF3;  pGO[(q * 4 + 3) * 128 + r] = aGO3;
        if (t + 1 < TLEN) xb4[((t + 1) & 1) * 512 + tid] = nx;
        __syncthreads();

        // reduce 4 k-quarters + activations; thread owns (r2, s2)
        ull sIF = pIF[s2 * 128 + r2];
        add2(sIF, pIF[(4 + s2) * 128 + r2]);
        add2(sIF, pIF[(8 + s2) * 128 + r2]);
        add2(sIF, pIF[(12 + s2) * 128 + r2]);
        ull sGO = pGO[s2 * 128 + r2];
        add2(sGO, pGO[(4 + s2) * 128 + r2]);
        add2(sGO, pGO[(8 + s2) * 128 + r2]);
        add2(sGO, pGO[(12 + s2) * 128 + r2]);

        float gi, gf, gg, go;
        upk2(sIF, gi, gf); upk2(sGO, gg, go);
        const float* xb = (const float*)&xb4[(t & 1) * 512];
        gi += xb[s2 * 512 + r2];
        gf += xb[s2 * 512 + 128 + r2];
        gg += xb[s2 * 512 + 256 + r2];
        go += xb[s2 * 512 + 384 + r2];

        float i_ = __fdividef(1.f, 1.f + __expf(-gi));
        float f_ = __fdividef(1.f, 1.f + __expf(-gf));
        float o_ = __fdividef(1.f, 1.f + __expf(-go));
        float eg = __expf(-2.f * fabsf(gg));
        float g_ = copysignf(__fdividef(1.f - eg, 1.f + eg), gg);

        cst = f_ * cst + i_ * g_;
        float ec = __expf(-2.f * fabsf(cst));
        float th = copysignf(__fdividef(1.f - ec, 1.f + ec), cst);
        hsm[r2 * 4 + s2] = o_ * th;
        __syncthreads();
    }

    // ---- FC epilogue: out[seq][c] = h . W_fc[c,:] + b_fc[c] ----
    float* wfs = (float*)(smem + LS_PIF);   // reuse 32 KB partials region
    for (int idx = tid; idx < CH * HID; idx += 512) {
        int c = idx >> 7, j = idx & 127;
        wfs[j * 64 + c] = Wfc[idx];         // transposed: [j][c]
    }
    __syncthreads();
    if (tid < 256) {
        int c = tid & 63, s = tid >> 6;
        float acc = bfc[c];
#pragma unroll 8
        for (int j = 0; j < HID; j++)
            acc += hsm[j * 4 + s] * wfs[j * 64 + c];
        out[(s0 + s) * 64 + c] = acc;
    }
}

// ---------------- launch ----------------
extern "C" void kernel_launch(void* const* d_in, const int* in_sizes, int n_in,
                              void* d_out, int out_size)
{
    const float* x   = (const float*)d_in[0];
    const float* Wih = (const float*)d_in[1];
    const float* Whh = (const float*)d_in[2];
    const float* bih = (const float*)d_in[3];
    const float* bhh = (const float*)d_in[4];
    const float* Wfc = (const float*)d_in[5];
    const float* bfc = (const float*)d_in[6];
    float* out = (float*)d_out;

    cudaFuncSetAttribute(lstm_kernel, cudaFuncAttributeMaxDynamicSharedMemorySize, LS_TOTAL);

    prep_kernel<<<256, 256>>>(Wih, Whh, bih, bhh);
    transp_kernel<<<dim3(TLEN, 16), 256>>>(x);
    gemm_kernel<<<dim3(NROW / 64, G4 / 64), 256>>>();
    lstm_kernel<<<120, 512, LS_TOTAL>>>(Wfc, bfc, out);
}